// round 1
// baseline (speedup 1.0000x reference)
#include <cuda_runtime.h>

#define TT 512
#define BB 512
#define KK 8
#define VV 5
#define HH 30
#define NLL 4

// ping-pong sequence buffers (T, B, H) fp32
__device__ float g_bufA[(size_t)TT * BB * HH];
__device__ float g_bufB[(size_t)TT * BB * HH];

// ---------- helpers ----------
__device__ __forceinline__ unsigned long long pk2(float lo, float hi) {
    unsigned long long r;
    asm("mov.b64 %0, {%1,%2};" : "=l"(r) : "f"(lo), "f"(hi));
    return r;
}
__device__ __forceinline__ void upk2(unsigned long long v, float& lo, float& hi) {
    asm("mov.b64 {%0,%1}, %2;" : "=f"(lo), "=f"(hi) : "l"(v));
}
__device__ __forceinline__ unsigned long long ffma2(unsigned long long a,
                                                    unsigned long long b,
                                                    unsigned long long c) {
    unsigned long long d;
    asm("fma.rn.f32x2 %0, %1, %2, %3;" : "=l"(d) : "l"(a), "l"(b), "l"(c));
    return d;
}
__device__ __forceinline__ float sigmf(float x) {
    return __fdividef(1.f, 1.f + __expf(-x));
}

// ---------- kernel 1: embedding + relu + mean over K ----------
__global__ void embed_kernel(const int* __restrict__ x,
                             const float* __restrict__ w,
                             const float* __restrict__ emb) {
    __shared__ float se[VV * HH];
    for (int i = threadIdx.x; i < VV * HH; i += blockDim.x) se[i] = emb[i];
    __syncthreads();
    int idx = blockIdx.x * blockDim.x + threadIdx.x;  // over T*B*H (exact)
    int j = idx % HH;
    size_t tb = (size_t)(idx / HH);
    const int* xp = x + tb * KK;
    const float* wp = w + tb * KK;
    float s = 0.f;
#pragma unroll
    for (int k = 0; k < KK; k++) {
        float e = se[xp[k] * HH + j] * wp[k];
        s += fmaxf(e, 0.f);
    }
    g_bufA[idx] = s * (1.f / KK);
}

// ---------- kernel 2: one LSTM layer ----------
// grid = B/4 CTAs, block = 120 threads. tid = j*4 + g (j hidden unit, g gate).
// Each CTA owns 4 batch elements; smem holds {x_t, h_{t-1}} interleaved as float4
// per (k, batch-pair); gate matvec done with packed f32x2 FMAs, weights in regs.
__global__ void __launch_bounds__(120, 1)
lstm_kernel(const float* __restrict__ Wih, const float* __restrict__ Whh,
            const float* __restrict__ bih, const float* __restrict__ bhh,
            int inIsA) {
    const float* __restrict__ in  = inIsA ? g_bufA : g_bufB;
    float* __restrict__ out       = inIsA ? g_bufB : g_bufA;

    __shared__ float4 xh[2][HH][2];  // [buf][k][pair] = {x(2p), x(2p+1), h(2p), h(2p+1)}

    const int tid = threadIdx.x;     // 0..119
    const int j = tid >> 2;
    const int g = tid & 3;
    const int b0 = blockIdx.x * 4;
    const int row = g * HH + j;      // gate row in (4H, H) weight

    unsigned long long wih[HH], whh[HH];
#pragma unroll
    for (int k = 0; k < HH; k++) {
        float a = Wih[row * HH + k];
        float b = Whh[row * HH + k];
        wih[k] = pk2(a, a);
        whh[k] = pk2(b, b);
    }
    float bias = bih[row] + bhh[row];
    const unsigned long long bias2 = pk2(bias, bias);
    const unsigned long long zero2 = pk2(0.f, 0.f);

    float c0 = 0.f, c1 = 0.f, c2 = 0.f, c3 = 0.f;

    // activation constants: g==2 -> tanh = 2*sigm(2x)-1, else sigmoid
    const float nm = (g == 2) ? 2.f : 1.f;
    const float na = (g == 2) ? -1.f : 0.f;

    // prologue: load x_0, h_init = 0 into buffer 0
    {
        int bl = tid / HH, k = tid - bl * HH;
        float xv = in[(size_t)(b0 + bl) * HH + k];
        float* p = (float*)&xh[0][k][bl >> 1];
        p[bl & 1] = xv;
        p[2 + (bl & 1)] = 0.f;
    }
    __syncthreads();

    const unsigned wm = __activemask();
    const int base = (tid & 31) & ~3;

    for (int t = 0; t < TT; t++) {
        const int cur = t & 1, nxt = cur ^ 1;

        unsigned long long a0 = bias2, e0 = zero2, a1 = bias2, e1 = zero2;
#pragma unroll
        for (int k = 0; k < HH; k++) {
            float4 v0 = xh[cur][k][0];
            float4 v1 = xh[cur][k][1];
            unsigned long long x0 = pk2(v0.x, v0.y), h0 = pk2(v0.z, v0.w);
            unsigned long long x1 = pk2(v1.x, v1.y), h1 = pk2(v1.z, v1.w);
            if (k & 1) {
                e0 = ffma2(wih[k], x0, e0); e0 = ffma2(whh[k], h0, e0);
                e1 = ffma2(wih[k], x1, e1); e1 = ffma2(whh[k], h1, e1);
            } else {
                a0 = ffma2(wih[k], x0, a0); a0 = ffma2(whh[k], h0, a0);
                a1 = ffma2(wih[k], x1, a1); a1 = ffma2(whh[k], h1, a1);
            }
        }
        float s0, s1, s2, s3, u0, u1, u2, u3;
        upk2(a0, s0, s1); upk2(e0, u0, u1);
        upk2(a1, s2, s3); upk2(e1, u2, u3);
        float gg0 = s0 + u0, gg1 = s1 + u1, gg2 = s2 + u2, gg3 = s3 + u3;

        // per-lane gate activation
        float act0 = fmaf(nm, sigmf(nm * gg0), na);
        float act1 = fmaf(nm, sigmf(nm * gg1), na);
        float act2 = fmaf(nm, sigmf(nm * gg2), na);
        float act3 = fmaf(nm, sigmf(nm * gg3), na);

        // exchange gates within 4-lane group, update cell, compute h
        float h0v, h1v, h2v, h3v;
        {
            float i_ = __shfl_sync(wm, act0, base + 0);
            float f_ = __shfl_sync(wm, act0, base + 1);
            float g_ = __shfl_sync(wm, act0, base + 2);
            float o_ = __shfl_sync(wm, act0, base + 3);
            c0 = fmaf(f_, c0, i_ * g_);
            h0v = o_ * fmaf(2.f, sigmf(2.f * c0), -1.f);
        }
        {
            float i_ = __shfl_sync(wm, act1, base + 0);
            float f_ = __shfl_sync(wm, act1, base + 1);
            float g_ = __shfl_sync(wm, act1, base + 2);
            float o_ = __shfl_sync(wm, act1, base + 3);
            c1 = fmaf(f_, c1, i_ * g_);
            h1v = o_ * fmaf(2.f, sigmf(2.f * c1), -1.f);
        }
        {
            float i_ = __shfl_sync(wm, act2, base + 0);
            float f_ = __shfl_sync(wm, act2, base + 1);
            float g_ = __shfl_sync(wm, act2, base + 2);
            float o_ = __shfl_sync(wm, act2, base + 3);
            c2 = fmaf(f_, c2, i_ * g_);
            h2v = o_ * fmaf(2.f, sigmf(2.f * c2), -1.f);
        }
        {
            float i_ = __shfl_sync(wm, act3, base + 0);
            float f_ = __shfl_sync(wm, act3, base + 1);
            float g_ = __shfl_sync(wm, act3, base + 2);
            float o_ = __shfl_sync(wm, act3, base + 3);
            c3 = fmaf(f_, c3, i_ * g_);
            h3v = o_ * fmaf(2.f, sigmf(2.f * c3), -1.f);
        }

        // lane g publishes h for batch element bb == g
        float hv = (g == 0) ? h0v : (g == 1) ? h1v : (g == 2) ? h2v : h3v;
        ((float*)&xh[nxt][j][g >> 1])[2 + (g & 1)] = hv;
        out[((size_t)t * BB + b0 + g) * HH + j] = hv;

        // prefetch x_{t+1} into next buffer
        if (t + 1 < TT) {
            int bl = tid / HH, k = tid - bl * HH;
            float xv = in[((size_t)(t + 1) * BB + b0 + bl) * HH + k];
            ((float*)&xh[nxt][k][bl >> 1])[bl & 1] = xv;
        }
        __syncthreads();
    }
}

// ---------- kernel 3: attention pooling + FC + softmax ----------
__global__ void __launch_bounds__(256)
attn_kernel(int encIsA,
            const float* __restrict__ W1, const float* __restrict__ b1,
            const float* __restrict__ W2, const float* __restrict__ b2,
            const float* __restrict__ fcW, const float* __restrict__ fcb,
            float* __restrict__ outp) {
    const float* __restrict__ enc = encIsA ? g_bufA : g_bufB;
    const int b = blockIdx.x, tid = threadIdx.x;

    __shared__ float4 sW1[HH * 16];  // (30, 64) as float4
    __shared__ float4 sB1[16];
    __shared__ float4 sW2[16];
    __shared__ float se[TT];
    __shared__ float sred[8];
    __shared__ float swsum[8][HH];
    __shared__ float spool[HH];
    __shared__ float sscal[2];

    for (int i = tid; i < HH * 16; i += 256) sW1[i] = ((const float4*)W1)[i];
    if (tid < 16) {
        sB1[tid] = ((const float4*)b1)[tid];
        sW2[tid] = ((const float4*)W2)[tid];
    }
    __syncthreads();

    const float b2v = b2[0];
    for (int tt = tid; tt < TT; tt += 256) {
        const float* hp = enc + ((size_t)tt * BB + b) * HH;
        float4 acc[16];
#pragma unroll
        for (int q = 0; q < 16; q++) acc[q] = sB1[q];
        for (int jj = 0; jj < HH; jj++) {
            float hj = __ldg(hp + jj);
#pragma unroll
            for (int q = 0; q < 16; q++) {
                float4 wv = sW1[jj * 16 + q];
                acc[q].x = fmaf(hj, wv.x, acc[q].x);
                acc[q].y = fmaf(hj, wv.y, acc[q].y);
                acc[q].z = fmaf(hj, wv.z, acc[q].z);
                acc[q].w = fmaf(hj, wv.w, acc[q].w);
            }
        }
        float e = b2v;
#pragma unroll
        for (int q = 0; q < 16; q++) {
            float4 w2 = sW2[q];
            e += fmaxf(acc[q].x, 0.f) * w2.x + fmaxf(acc[q].y, 0.f) * w2.y +
                 fmaxf(acc[q].z, 0.f) * w2.z + fmaxf(acc[q].w, 0.f) * w2.w;
        }
        se[tt] = e;
    }
    __syncthreads();

    // softmax over T
    float m = -1e30f;
    for (int i = tid; i < TT; i += 256) m = fmaxf(m, se[i]);
#pragma unroll
    for (int o = 16; o; o >>= 1) m = fmaxf(m, __shfl_xor_sync(0xffffffffu, m, o));
    if ((tid & 31) == 0) sred[tid >> 5] = m;
    __syncthreads();
    if (tid < 32) {
        float v = (tid < 8) ? sred[tid] : -1e30f;
#pragma unroll
        for (int o = 4; o; o >>= 1) v = fmaxf(v, __shfl_xor_sync(0xffffffffu, v, o));
        if (tid == 0) sscal[0] = v;
    }
    __syncthreads();
    const float M = sscal[0];
    float ssum = 0.f;
    for (int i = tid; i < TT; i += 256) {
        float e = __expf(se[i] - M);
        se[i] = e;
        ssum += e;
    }
#pragma unroll
    for (int o = 16; o; o >>= 1) ssum += __shfl_xor_sync(0xffffffffu, ssum, o);
    if ((tid & 31) == 0) sred[tid >> 5] = ssum;
    __syncthreads();
    if (tid < 32) {
        float v = (tid < 8) ? sred[tid] : 0.f;
#pragma unroll
        for (int o = 4; o; o >>= 1) v += __shfl_xor_sync(0xffffffffu, v, o);
        if (tid == 0) sscal[1] = __fdividef(1.f, v);
    }
    __syncthreads();
    const float inv = sscal[1];

    // weighted sum over time
    float pa[HH];
#pragma unroll
    for (int jj = 0; jj < HH; jj++) pa[jj] = 0.f;
    for (int tt = tid; tt < TT; tt += 256) {
        float wgt = se[tt] * inv;
        const float* hp = enc + ((size_t)tt * BB + b) * HH;
#pragma unroll
        for (int jj = 0; jj < HH; jj++) pa[jj] = fmaf(wgt, __ldg(hp + jj), pa[jj]);
    }
#pragma unroll
    for (int jj = 0; jj < HH; jj++) {
#pragma unroll
        for (int o = 16; o; o >>= 1) pa[jj] += __shfl_xor_sync(0xffffffffu, pa[jj], o);
    }
    if ((tid & 31) == 0) {
        int w = tid >> 5;
#pragma unroll
        for (int jj = 0; jj < HH; jj++) swsum[w][jj] = pa[jj];
    }
    __syncthreads();
    if (tid < HH) {
        float s = 0.f;
#pragma unroll
        for (int w = 0; w < 8; w++) s += swsum[w][tid];
        spool[tid] = s;
    }
    __syncthreads();
    if (tid == 0) {
        float l0 = fcb[0], l1 = fcb[1], l2 = fcb[2];
#pragma unroll
        for (int jj = 0; jj < HH; jj++) {
            float p = spool[jj];
            l0 = fmaf(p, fcW[jj * 3 + 0], l0);
            l1 = fmaf(p, fcW[jj * 3 + 1], l1);
            l2 = fmaf(p, fcW[jj * 3 + 2], l2);
        }
        float mx = fmaxf(l0, fmaxf(l1, l2));
        float e0 = __expf(l0 - mx), e1 = __expf(l1 - mx), e2 = __expf(l2 - mx);
        float is = __fdividef(1.f, e0 + e1 + e2);
        outp[b * 3 + 0] = e0 * is;
        outp[b * 3 + 1] = e1 * is;
        outp[b * 3 + 2] = e2 * is;
    }
}

// ---------- launch ----------
extern "C" void kernel_launch(void* const* d_in, const int* in_sizes, int n_in,
                              void* d_out, int out_size) {
    const int*   x   = (const int*)  d_in[0];
    const float* wx  = (const float*)d_in[1];
    const float* emb = (const float*)d_in[2];
    const float* Wih = (const float*)d_in[3];
    const float* Whh = (const float*)d_in[4];
    const float* bih = (const float*)d_in[5];
    const float* bhh = (const float*)d_in[6];
    const float* aW1 = (const float*)d_in[7];
    const float* ab1 = (const float*)d_in[8];
    const float* aW2 = (const float*)d_in[9];
    const float* ab2 = (const float*)d_in[10];
    const float* fcW = (const float*)d_in[11];
    const float* fcb = (const float*)d_in[12];
    float* outp = (float*)d_out;

    embed_kernel<<<(TT * BB * HH) / 256, 256>>>(x, wx, emb);

    int inA = 1;
    for (int l = 0; l < NLL; l++) {
        lstm_kernel<<<BB / 4, 120>>>(Wih + l * 4 * HH * HH, Whh + l * 4 * HH * HH,
                                     bih + l * 4 * HH, bhh + l * 4 * HH, inA);
        inA ^= 1;
    }

    attn_kernel<<<BB, 256>>>(inA, aW1, ab1, aW2, ab2, fcW, fcb, outp);
}

// round 2
// speedup vs baseline: 1.0509x; 1.0509x over previous
#include <cuda_runtime.h>

#define TT 512
#define BB 512
#define KK 8
#define VV 5
#define HH 30
#define NLL 4

// ping-pong sequence buffers (T, B, H) fp32
__device__ float g_bufA[(size_t)TT * BB * HH];
__device__ float g_bufB[(size_t)TT * BB * HH];

// ---------- helpers ----------
__device__ __forceinline__ unsigned long long pk2(float lo, float hi) {
    unsigned long long r;
    asm("mov.b64 %0, {%1,%2};" : "=l"(r) : "f"(lo), "f"(hi));
    return r;
}
__device__ __forceinline__ void upk2(unsigned long long v, float& lo, float& hi) {
    asm("mov.b64 {%0,%1}, %2;" : "=f"(lo), "=f"(hi) : "l"(v));
}
__device__ __forceinline__ unsigned long long ffma2(unsigned long long a,
                                                    unsigned long long b,
                                                    unsigned long long c) {
    unsigned long long d;
    asm("fma.rn.f32x2 %0, %1, %2, %3;" : "=l"(d) : "l"(a), "l"(b), "l"(c));
    return d;
}
__device__ __forceinline__ float sigmf(float x) {
    return __fdividef(1.f, 1.f + __expf(-x));
}

// ---------- kernel 1: embedding + relu + mean over K ----------
__global__ void embed_kernel(const int* __restrict__ x,
                             const float* __restrict__ w,
                             const float* __restrict__ emb) {
    __shared__ float se[VV * HH];
    for (int i = threadIdx.x; i < VV * HH; i += blockDim.x) se[i] = emb[i];
    __syncthreads();
    int idx = blockIdx.x * blockDim.x + threadIdx.x;  // over T*B*H (exact)
    int j = idx % HH;
    size_t tb = (size_t)(idx / HH);
    const int* xp = x + tb * KK;
    const float* wp = w + tb * KK;
    float s = 0.f;
#pragma unroll
    for (int k = 0; k < KK; k++) {
        float e = se[xp[k] * HH + j] * wp[k];
        s += fmaxf(e, 0.f);
    }
    g_bufA[idx] = s * (1.f / KK);
}

// ---------- kernel 2: all 4 LSTM layers, fused ----------
// grid = B/4 CTAs, block = 240 threads.
// tid = pair*120 + j*4 + g. Each thread computes gate-row (g*30+j) for the TWO
// batch elements of its pair. Weights packed as f32x2 (wih_k, whh_k); operands
// come straight out of a float4 smem tile (x0,h0,x1,h1) with no repacking.
__global__ void __launch_bounds__(240, 1)
lstm4_kernel(const float* __restrict__ Wih_all, const float* __restrict__ Whh_all,
             const float* __restrict__ bih_all, const float* __restrict__ bhh_all) {
    __shared__ float4 xh[2][HH][2];  // [buf][k][pair] = {x(e0), h(e0), x(e1), h(e1)}

    const int tid = threadIdx.x;      // 0..239
    const int pair = tid / 120;       // 0,1
    const int r = tid - pair * 120;   // 0..119
    const int j = r >> 2;
    const int g = r & 3;
    const int b0 = blockIdx.x * 4;
    const int row = g * HH + j;

    // x prefetch role: 120 threads (pair==0) load 4x30 x values per step
    const int pf_bl = r / HH;            // batch-local 0..3 (valid when pair==0)
    const int pf_k = r - pf_bl * HH;

    const unsigned wm = __activemask();
    const int base = (tid & 31) & ~3;

    // activation constants: g==2 -> tanh = 2*sigm(2x)-1, else sigmoid
    const float nm = (g == 2) ? 2.f : 1.f;
    const float na = (g == 2) ? -1.f : 0.f;

    for (int l = 0; l < NLL; l++) {
        const float* __restrict__ in  = (l & 1) ? g_bufB : g_bufA;
        float* __restrict__ out       = (l & 1) ? g_bufA : g_bufB;
        const float* Wih = Wih_all + l * 4 * HH * HH;
        const float* Whh = Whh_all + l * 4 * HH * HH;

        unsigned long long w2[HH];
#pragma unroll
        for (int k = 0; k < HH; k++)
            w2[k] = pk2(Wih[row * HH + k], Whh[row * HH + k]);
        const float bias = bih_all[l * 4 * HH + row] + bhh_all[l * 4 * HH + row];
        const unsigned long long biasA = pk2(bias, 0.f);
        const unsigned long long zero2 = pk2(0.f, 0.f);

        float c0 = 0.f, c1 = 0.f;

        // prologue: x_0 and h=0 into buffer 0
        if (pair == 0) {
            float xv = in[(size_t)(b0 + pf_bl) * HH + pf_k];
            float* p = (float*)&xh[0][pf_k][pf_bl >> 1];
            p[(pf_bl & 1) * 2] = xv;
            p[(pf_bl & 1) * 2 + 1] = 0.f;
        }
        __syncthreads();

        for (int t = 0; t < TT; t++) {
            const int cur = t & 1, nxt = cur ^ 1;

            // gate matvec: two chains per element (even/odd k)
            unsigned long long aA0 = biasA, aB0 = zero2;
            unsigned long long aA1 = biasA, aB1 = zero2;
#pragma unroll
            for (int k = 0; k < HH; k++) {
                float4 v = xh[cur][k][pair];
                unsigned long long p0 = pk2(v.x, v.y);
                unsigned long long p1 = pk2(v.z, v.w);
                if (k & 1) {
                    aB0 = ffma2(w2[k], p0, aB0);
                    aB1 = ffma2(w2[k], p1, aB1);
                } else {
                    aA0 = ffma2(w2[k], p0, aA0);
                    aA1 = ffma2(w2[k], p1, aA1);
                }
            }
            float xa, xb, xc, xd;
            upk2(aA0, xa, xb);
            upk2(aB0, xc, xd);
            float g0 = (xa + xb) + (xc + xd);
            upk2(aA1, xa, xb);
            upk2(aB1, xc, xd);
            float g1 = (xa + xb) + (xc + xd);

            // own-gate activations for both elements
            float act0 = fmaf(nm, sigmf(nm * g0), na);
            float act1 = fmaf(nm, sigmf(nm * g1), na);

            // exchange gates within 4-lane group (same j, same pair)
            float i0 = __shfl_sync(wm, act0, base + 0);
            float f0 = __shfl_sync(wm, act0, base + 1);
            float gg0 = __shfl_sync(wm, act0, base + 2);
            float o0 = __shfl_sync(wm, act0, base + 3);
            float i1 = __shfl_sync(wm, act1, base + 0);
            float f1 = __shfl_sync(wm, act1, base + 1);
            float gg1 = __shfl_sync(wm, act1, base + 2);
            float o1 = __shfl_sync(wm, act1, base + 3);

            c0 = fmaf(f0, c0, i0 * gg0);
            c1 = fmaf(f1, c1, i1 * gg1);
            float h0 = o0 * fmaf(2.f, sigmf(2.f * c0), -1.f);
            float h1 = o1 * fmaf(2.f, sigmf(2.f * c1), -1.f);

            // one lane per group publishes h (smem + global)
            if (g == 0) {
                float* p = (float*)&xh[nxt][j][pair];
                p[1] = h0;
                p[3] = h1;
                size_t ob = ((size_t)t * BB + b0 + 2 * pair) * HH + j;
                out[ob] = h0;
                out[ob + HH] = h1;
            }

            // prefetch x_{t+1}
            if (pair == 0 && t + 1 < TT) {
                float xv = in[((size_t)(t + 1) * BB + b0 + pf_bl) * HH + pf_k];
                ((float*)&xh[nxt][pf_k][pf_bl >> 1])[(pf_bl & 1) * 2] = xv;
            }
            __syncthreads();
        }
        __syncthreads();  // layer boundary: all global h writes visible CTA-wide
    }
}

// ---------- kernel 3: attention pooling + FC + softmax ----------
__global__ void __launch_bounds__(256)
attn_kernel(const float* __restrict__ W1, const float* __restrict__ b1,
            const float* __restrict__ W2, const float* __restrict__ b2,
            const float* __restrict__ fcW, const float* __restrict__ fcb,
            float* __restrict__ outp) {
    const float* __restrict__ enc = g_bufA;  // 4 layers: A->B->A->B->A... l=3 writes A
    const int b = blockIdx.x, tid = threadIdx.x;

    __shared__ float4 sW1[HH * 16];  // (30, 64) as float4
    __shared__ float4 sB1[16];
    __shared__ float4 sW2[16];
    __shared__ float se[TT];
    __shared__ float sred[8];
    __shared__ float swsum[8][HH];
    __shared__ float spool[HH];
    __shared__ float sscal[2];

    for (int i = tid; i < HH * 16; i += 256) sW1[i] = ((const float4*)W1)[i];
    if (tid < 16) {
        sB1[tid] = ((const float4*)b1)[tid];
        sW2[tid] = ((const float4*)W2)[tid];
    }
    __syncthreads();

    const float b2v = b2[0];
    for (int tt = tid; tt < TT; tt += 256) {
        const float* hp = enc + ((size_t)tt * BB + b) * HH;
        float4 acc[16];
#pragma unroll
        for (int q = 0; q < 16; q++) acc[q] = sB1[q];
        for (int jj = 0; jj < HH; jj++) {
            float hj = __ldg(hp + jj);
#pragma unroll
            for (int q = 0; q < 16; q++) {
                float4 wv = sW1[jj * 16 + q];
                acc[q].x = fmaf(hj, wv.x, acc[q].x);
                acc[q].y = fmaf(hj, wv.y, acc[q].y);
                acc[q].z = fmaf(hj, wv.z, acc[q].z);
                acc[q].w = fmaf(hj, wv.w, acc[q].w);
            }
        }
        float e = b2v;
#pragma unroll
        for (int q = 0; q < 16; q++) {
            float4 w2 = sW2[q];
            e += fmaxf(acc[q].x, 0.f) * w2.x + fmaxf(acc[q].y, 0.f) * w2.y +
                 fmaxf(acc[q].z, 0.f) * w2.z + fmaxf(acc[q].w, 0.f) * w2.w;
        }
        se[tt] = e;
    }
    __syncthreads();

    // softmax over T
    float m = -1e30f;
    for (int i = tid; i < TT; i += 256) m = fmaxf(m, se[i]);
#pragma unroll
    for (int o = 16; o; o >>= 1) m = fmaxf(m, __shfl_xor_sync(0xffffffffu, m, o));
    if ((tid & 31) == 0) sred[tid >> 5] = m;
    __syncthreads();
    if (tid < 32) {
        float v = (tid < 8) ? sred[tid] : -1e30f;
#pragma unroll
        for (int o = 4; o; o >>= 1) v = fmaxf(v, __shfl_xor_sync(0xffffffffu, v, o));
        if (tid == 0) sscal[0] = v;
    }
    __syncthreads();
    const float M = sscal[0];
    float ssum = 0.f;
    for (int i = tid; i < TT; i += 256) {
        float e = __expf(se[i] - M);
        se[i] = e;
        ssum += e;
    }
#pragma unroll
    for (int o = 16; o; o >>= 1) ssum += __shfl_xor_sync(0xffffffffu, ssum, o);
    if ((tid & 31) == 0) sred[tid >> 5] = ssum;
    __syncthreads();
    if (tid < 32) {
        float v = (tid < 8) ? sred[tid] : 0.f;
#pragma unroll
        for (int o = 4; o; o >>= 1) v += __shfl_xor_sync(0xffffffffu, v, o);
        if (tid == 0) sscal[1] = __fdividef(1.f, v);
    }
    __syncthreads();
    const float inv = sscal[1];

    // weighted sum over time
    float pa[HH];
#pragma unroll
    for (int jj = 0; jj < HH; jj++) pa[jj] = 0.f;
    for (int tt = tid; tt < TT; tt += 256) {
        float wgt = se[tt] * inv;
        const float* hp = enc + ((size_t)tt * BB + b) * HH;
#pragma unroll
        for (int jj = 0; jj < HH; jj++) pa[jj] = fmaf(wgt, __ldg(hp + jj), pa[jj]);
    }
#pragma unroll
    for (int jj = 0; jj < HH; jj++) {
#pragma unroll
        for (int o = 16; o; o >>= 1) pa[jj] += __shfl_xor_sync(0xffffffffu, pa[jj], o);
    }
    if ((tid & 31) == 0) {
        int w = tid >> 5;
#pragma unroll
        for (int jj = 0; jj < HH; jj++) swsum[w][jj] = pa[jj];
    }
    __syncthreads();
    if (tid < HH) {
        float s = 0.f;
#pragma unroll
        for (int w = 0; w < 8; w++) s += swsum[w][tid];
        spool[tid] = s;
    }
    __syncthreads();
    if (tid == 0) {
        float l0 = fcb[0], l1 = fcb[1], l2 = fcb[2];
#pragma unroll
        for (int jj = 0; jj < HH; jj++) {
            float p = spool[jj];
            l0 = fmaf(p, fcW[jj * 3 + 0], l0);
            l1 = fmaf(p, fcW[jj * 3 + 1], l1);
            l2 = fmaf(p, fcW[jj * 3 + 2], l2);
        }
        float mx = fmaxf(l0, fmaxf(l1, l2));
        float e0 = __expf(l0 - mx), e1 = __expf(l1 - mx), e2 = __expf(l2 - mx);
        float is = __fdividef(1.f, e0 + e1 + e2);
        outp[b * 3 + 0] = e0 * is;
        outp[b * 3 + 1] = e1 * is;
        outp[b * 3 + 2] = e2 * is;
    }
}

// ---------- launch ----------
extern "C" void kernel_launch(void* const* d_in, const int* in_sizes, int n_in,
                              void* d_out, int out_size) {
    const int*   x   = (const int*)  d_in[0];
    const float* wx  = (const float*)d_in[1];
    const float* emb = (const float*)d_in[2];
    const float* Wih = (const float*)d_in[3];
    const float* Whh = (const float*)d_in[4];
    const float* bih = (const float*)d_in[5];
    const float* bhh = (const float*)d_in[6];
    const float* aW1 = (const float*)d_in[7];
    const float* ab1 = (const float*)d_in[8];
    const float* aW2 = (const float*)d_in[9];
    const float* ab2 = (const float*)d_in[10];
    const float* fcW = (const float*)d_in[11];
    const float* fcb = (const float*)d_in[12];
    float* outp = (float*)d_out;

    embed_kernel<<<(TT * BB * HH) / 256, 256>>>(x, wx, emb);
    lstm4_kernel<<<BB / 4, 240>>>(Wih, Whh, bih, bhh);
    attn_kernel<<<BB, 256>>>(aW1, ab1, aW2, ab2, fcW, fcb, outp);
}

// round 3
// speedup vs baseline: 1.7518x; 1.6669x over previous
#include <cuda_runtime.h>

#define TT 512
#define BB 512
#define KK 8
#define VV 5
#define HH 30
#define NLL 4

// ping-pong sequence buffers (T, B, H) fp32
__device__ float g_bufA[(size_t)TT * BB * HH];
__device__ float g_bufB[(size_t)TT * BB * HH];

// ---------- helpers ----------
__device__ __forceinline__ unsigned long long pk2(float lo, float hi) {
    unsigned long long r;
    asm("mov.b64 %0, {%1,%2};" : "=l"(r) : "f"(lo), "f"(hi));
    return r;
}
__device__ __forceinline__ void upk2(unsigned long long v, float& lo, float& hi) {
    asm("mov.b64 {%0,%1}, %2;" : "=f"(lo), "=f"(hi) : "l"(v));
}
__device__ __forceinline__ unsigned long long ffma2(unsigned long long a,
                                                    unsigned long long b,
                                                    unsigned long long c) {
    unsigned long long d;
    asm("fma.rn.f32x2 %0, %1, %2, %3;" : "=l"(d) : "l"(a), "l"(b), "l"(c));
    return d;
}
__device__ __forceinline__ float tanh_ap(float x) {
    float r;
    asm("tanh.approx.f32 %0, %1;" : "=f"(r) : "f"(x));
    return r;
}

// ---------- kernel 1: embedding + relu + mean over K ----------
__global__ void embed_kernel(const int* __restrict__ x,
                             const float* __restrict__ w,
                             const float* __restrict__ emb) {
    __shared__ float se[VV * HH];
    for (int i = threadIdx.x; i < VV * HH; i += blockDim.x) se[i] = emb[i];
    __syncthreads();
    int idx = blockIdx.x * blockDim.x + threadIdx.x;  // over T*B*H (exact)
    int j = idx % HH;
    size_t tb = (size_t)(idx / HH);
    const int* xp = x + tb * KK;
    const float* wp = w + tb * KK;
    float s = 0.f;
#pragma unroll
    for (int k = 0; k < KK; k++) {
        float e = se[xp[k] * HH + j] * wp[k];
        s += fmaxf(e, 0.f);
    }
    g_bufA[idx] = s * (1.f / KK);
}

// ---------- kernel 2: all 4 LSTM layers, fused ----------
// grid = B/2 = 256 CTAs (2 CTAs/SM for latency overlap), block = 240 threads.
// tid = el*120 + j*4 + g : one gate-row (g*30+j) of one batch element.
// smem tile per element: interleaved (x_k, h_k) pairs so each LDS.128 yields
// TWO aligned f32x2 operands consumed directly by fma.rn.f32x2 (zero pack movs).
__global__ void __launch_bounds__(240, 2)
lstm4_kernel(const float* __restrict__ Wih_all, const float* __restrict__ Whh_all,
             const float* __restrict__ bih_all, const float* __restrict__ bhh_all) {
    __shared__ __align__(16) float xh[2][2][64];  // [buf][el][2k: x_k, 2k+1: h_k]

    const int tid = threadIdx.x;        // 0..239
    const int el = tid / 120;           // batch element within chunk (0,1)
    const int r = tid - el * 120;       // 0..119
    const int j = r >> 2;
    const int g = r & 3;
    const int b0 = blockIdx.x * 2;
    const int row = g * HH + j;

    const bool xload = (tid < 60);      // x prefetch role
    const int xe = tid / HH;            // 0,1 (valid when xload)
    const int xk = tid - xe * HH;

    const int base = (tid & 31) & ~3;
    const unsigned qmask = 0xFu << base;

    // activation: g==2 -> tanh(x); else sigmoid(x) = 0.5*tanh(0.5x)+0.5
    const float tm = (g == 2) ? 1.f : 0.5f;
    const float ts = (g == 2) ? 1.f : 0.5f;
    const float ta = (g == 2) ? 0.f : 0.5f;

#pragma unroll 1
    for (int l = 0; l < NLL; l++) {
        const float* __restrict__ in  = (l & 1) ? g_bufB : g_bufA;
        float* __restrict__ out       = (l & 1) ? g_bufA : g_bufB;
        const float* Wih = Wih_all + l * 4 * HH * HH;
        const float* Whh = Whh_all + l * 4 * HH * HH;

        unsigned long long w2[HH];  // (wih_k, whh_k)
#pragma unroll
        for (int k = 0; k < HH; k++)
            w2[k] = pk2(Wih[row * HH + k], Whh[row * HH + k]);
        const float bias = bih_all[l * 4 * HH + row] + bhh_all[l * 4 * HH + row];
        const unsigned long long biasA = pk2(bias, 0.f);
        const unsigned long long zero2 = pk2(0.f, 0.f);

        float c = 0.f;
        float xn1 = 0.f, xn2 = 0.f;

        // prologue: x_0 + h=0 into buf 0; x_1 into reg
        if (xload) {
            xh[0][xe][2 * xk] = in[(size_t)(b0 + xe) * HH + xk];
            xh[0][xe][2 * xk + 1] = 0.f;
            xn1 = in[((size_t)BB + b0 + xe) * HH + xk];
        }
        __syncthreads();

#define LSTM_STEP(T, CUR, NXT, XIN, XOUT)                                      \
        {                                                                      \
            if (xload && (T) + 2 < TT)                                         \
                XOUT = in[(((size_t)(T) + 2) * BB + b0 + xe) * HH + xk];       \
            const ulonglong2* rowp = (const ulonglong2*)&xh[CUR][el][0];       \
            unsigned long long a0 = biasA, a1 = zero2;                         \
            _Pragma("unroll")                                                  \
            for (int m = 0; m < 15; m++) {                                     \
                ulonglong2 v = rowp[m];                                        \
                a0 = ffma2(w2[2 * m], v.x, a0);                                \
                a1 = ffma2(w2[2 * m + 1], v.y, a1);                            \
            }                                                                  \
            float p0, p1, q0, q1;                                              \
            upk2(a0, p0, p1);                                                  \
            upk2(a1, q0, q1);                                                  \
            float gate = (p0 + p1) + (q0 + q1);                                \
            float act = fmaf(ts, tanh_ap(tm * gate), ta);                      \
            float i_ = __shfl_sync(qmask, act, base + 0);                      \
            float f_ = __shfl_sync(qmask, act, base + 1);                      \
            float g_ = __shfl_sync(qmask, act, base + 2);                      \
            float o_ = __shfl_sync(qmask, act, base + 3);                      \
            c = fmaf(f_, c, i_ * g_);                                          \
            float h = o_ * tanh_ap(c);                                         \
            if (xload && (T) + 1 < TT) xh[NXT][xe][2 * xk] = XIN;              \
            if (g == 0) {                                                      \
                xh[NXT][el][2 * j + 1] = h;                                    \
                out[((size_t)(T) * BB + b0 + el) * HH + j] = h;                \
            }                                                                  \
            __syncthreads();                                                   \
        }

#pragma unroll 1
        for (int t = 0; t < TT; t += 2) {
            LSTM_STEP(t, 0, 1, xn1, xn2)
            LSTM_STEP(t + 1, 1, 0, xn2, xn1)
        }
#undef LSTM_STEP
    }
}

// ---------- kernel 3: attention pooling + FC + softmax ----------
__global__ void __launch_bounds__(256)
attn_kernel(const float* __restrict__ W1, const float* __restrict__ b1,
            const float* __restrict__ W2, const float* __restrict__ b2,
            const float* __restrict__ fcW, const float* __restrict__ fcb,
            float* __restrict__ outp) {
    const float* __restrict__ enc = g_bufA;  // 4 layers: final output in A
    const int b = blockIdx.x, tid = threadIdx.x;

    __shared__ float4 sW1[HH * 16];  // (30, 64) as float4
    __shared__ float4 sB1[16];
    __shared__ float4 sW2[16];
    __shared__ float se[TT];
    __shared__ float sred[8];
    __shared__ float swsum[8][HH];
    __shared__ float spool[HH];
    __shared__ float sscal[2];

    for (int i = tid; i < HH * 16; i += 256) sW1[i] = ((const float4*)W1)[i];
    if (tid < 16) {
        sB1[tid] = ((const float4*)b1)[tid];
        sW2[tid] = ((const float4*)W2)[tid];
    }
    __syncthreads();

    const float b2v = b2[0];
    for (int tt = tid; tt < TT; tt += 256) {
        const float* hp = enc + ((size_t)tt * BB + b) * HH;
        float4 acc[16];
#pragma unroll
        for (int q = 0; q < 16; q++) acc[q] = sB1[q];
        for (int jj = 0; jj < HH; jj++) {
            float hj = __ldg(hp + jj);
#pragma unroll
            for (int q = 0; q < 16; q++) {
                float4 wv = sW1[jj * 16 + q];
                acc[q].x = fmaf(hj, wv.x, acc[q].x);
                acc[q].y = fmaf(hj, wv.y, acc[q].y);
                acc[q].z = fmaf(hj, wv.z, acc[q].z);
                acc[q].w = fmaf(hj, wv.w, acc[q].w);
            }
        }
        float e = b2v;
#pragma unroll
        for (int q = 0; q < 16; q++) {
            float4 w2 = sW2[q];
            e += fmaxf(acc[q].x, 0.f) * w2.x + fmaxf(acc[q].y, 0.f) * w2.y +
                 fmaxf(acc[q].z, 0.f) * w2.z + fmaxf(acc[q].w, 0.f) * w2.w;
        }
        se[tt] = e;
    }
    __syncthreads();

    // softmax over T
    float m = -1e30f;
    for (int i = tid; i < TT; i += 256) m = fmaxf(m, se[i]);
#pragma unroll
    for (int o = 16; o; o >>= 1) m = fmaxf(m, __shfl_xor_sync(0xffffffffu, m, o));
    if ((tid & 31) == 0) sred[tid >> 5] = m;
    __syncthreads();
    if (tid < 32) {
        float v = (tid < 8) ? sred[tid] : -1e30f;
#pragma unroll
        for (int o = 4; o; o >>= 1) v = fmaxf(v, __shfl_xor_sync(0xffffffffu, v, o));
        if (tid == 0) sscal[0] = v;
    }
    __syncthreads();
    const float M = sscal[0];
    float ssum = 0.f;
    for (int i = tid; i < TT; i += 256) {
        float e = __expf(se[i] - M);
        se[i] = e;
        ssum += e;
    }
#pragma unroll
    for (int o = 16; o; o >>= 1) ssum += __shfl_xor_sync(0xffffffffu, ssum, o);
    if ((tid & 31) == 0) sred[tid >> 5] = ssum;
    __syncthreads();
    if (tid < 32) {
        float v = (tid < 8) ? sred[tid] : 0.f;
#pragma unroll
        for (int o = 4; o; o >>= 1) v += __shfl_xor_sync(0xffffffffu, v, o);
        if (tid == 0) sscal[1] = __fdividef(1.f, v);
    }
    __syncthreads();
    const float inv = sscal[1];

    // weighted sum over time
    float pa[HH];
#pragma unroll
    for (int jj = 0; jj < HH; jj++) pa[jj] = 0.f;
    for (int tt = tid; tt < TT; tt += 256) {
        float wgt = se[tt] * inv;
        const float* hp = enc + ((size_t)tt * BB + b) * HH;
#pragma unroll
        for (int jj = 0; jj < HH; jj++) pa[jj] = fmaf(wgt, __ldg(hp + jj), pa[jj]);
    }
#pragma unroll
    for (int jj = 0; jj < HH; jj++) {
#pragma unroll
        for (int o = 16; o; o >>= 1) pa[jj] += __shfl_xor_sync(0xffffffffu, pa[jj], o);
    }
    if ((tid & 31) == 0) {
        int w = tid >> 5;
#pragma unroll
        for (int jj = 0; jj < HH; jj++) swsum[w][jj] = pa[jj];
    }
    __syncthreads();
    if (tid < HH) {
        float s = 0.f;
#pragma unroll
        for (int w = 0; w < 8; w++) s += swsum[w][tid];
        spool[tid] = s;
    }
    __syncthreads();
    if (tid == 0) {
        float l0 = fcb[0], l1 = fcb[1], l2 = fcb[2];
#pragma unroll
        for (int jj = 0; jj < HH; jj++) {
            float p = spool[jj];
            l0 = fmaf(p, fcW[jj * 3 + 0], l0);
            l1 = fmaf(p, fcW[jj * 3 + 1], l1);
            l2 = fmaf(p, fcW[jj * 3 + 2], l2);
        }
        float mx = fmaxf(l0, fmaxf(l1, l2));
        float e0 = __expf(l0 - mx), e1 = __expf(l1 - mx), e2 = __expf(l2 - mx);
        float is = __fdividef(1.f, e0 + e1 + e2);
        outp[b * 3 + 0] = e0 * is;
        outp[b * 3 + 1] = e1 * is;
        outp[b * 3 + 2] = e2 * is;
    }
}

// ---------- launch ----------
extern "C" void kernel_launch(void* const* d_in, const int* in_sizes, int n_in,
                              void* d_out, int out_size) {
    const int*   x   = (const int*)  d_in[0];
    const float* wx  = (const float*)d_in[1];
    const float* emb = (const float*)d_in[2];
    const float* Wih = (const float*)d_in[3];
    const float* Whh = (const float*)d_in[4];
    const float* bih = (const float*)d_in[5];
    const float* bhh = (const float*)d_in[6];
    const float* aW1 = (const float*)d_in[7];
    const float* ab1 = (const float*)d_in[8];
    const float* aW2 = (const float*)d_in[9];
    const float* ab2 = (const float*)d_in[10];
    const float* fcW = (const float*)d_in[11];
    const float* fcb = (const float*)d_in[12];
    float* outp = (float*)d_out;

    embed_kernel<<<(TT * BB * HH) / 256, 256>>>(x, wx, emb);
    lstm4_kernel<<<BB / 2, 240>>>(Wih, Whh, bih, bhh);
    attn_kernel<<<BB, 256>>>(aW1, ab1, aW2, ab2, fcW, fcb, outp);
}